// round 7
// baseline (speedup 1.0000x reference)
#include <cuda_runtime.h>
#include <cstdint>

#define SL   3264            // seq length L
#define KK   12
#define LPK  (SL / KK)       // 272
#define SS   8               // streams
#define BB   64              // batch
#define AA   4               // antennas
#define RR   (SL / 4)        // 816 (L / LOCC)
#define NOFF 21              // delay candidates -10..10
#define TILE 128             // l-tile for k_final
#define NTILE 26             // ceil(3264/128)
#define PDIM 816             // decimated length L/4

// ---- scratch (device-global: allocation-free contract) ----
__device__ int    g_m[SS * BB];                   // (t_off + ideal_peak) mod L
__device__ int    g_tt[SS * BB];                  // t_off mod L
__device__ float  g_pows[SS * BB * AA * NOFF];    // candidate powers per antenna
__device__ float2 g_havg[SS * BB * AA * RR];      // OCC-averaged channel, 13.4 MB

// ---- packed f32x2 helpers (sm_103a dual-lane fp32) ----
#define F2MUL(o, a, b)    asm("mul.rn.f32x2 %0, %1, %2;"      : "=l"(o) : "l"(a), "l"(b))
#define F2FMA(o, a, b, c) asm("fma.rn.f32x2 %0, %1, %2, %3;"  : "=l"(o) : "l"(a), "l"(b), "l"(c))
#define F2ADD(o, a, b)    asm("add.rn.f32x2 %0, %1, %2;"      : "=l"(o) : "l"(a), "l"(b))
#define SGNMASK 0x8000000080000000ULL

static __device__ __forceinline__ uint64_t pk2(float lo, float hi) {
    uint64_t r; asm("mov.b64 %0, {%1, %2};" : "=l"(r) : "f"(lo), "f"(hi)); return r;
}
static __device__ __forceinline__ float lo2(uint64_t v) {
    float a, b; asm("mov.b64 {%0, %1}, %2;" : "=f"(a), "=f"(b) : "l"(v)); return a;
}
static __device__ __forceinline__ float hi2(uint64_t v) {
    float a, b; asm("mov.b64 {%0, %1}, %2;" : "=f"(a), "=f"(b) : "l"(v)); return b;
}
static __device__ __forceinline__ uint64_t splat(float v) { return pk2(v, v); }

// fp32 2*pi/L, matching reference fp32 angle math
#define WF ((float)(6.283185307179586476925286766559 / 3264.0))

// fast phasor: e^{i th k}, k in [0, SL); reduce to (-pi, pi] for MUFU accuracy
static __device__ __forceinline__ float2 phasor(int k) {
    if (k > SL / 2) k -= SL;
    float s, c;
    __sincosf(WF * (float)k, &s, &c);
    return make_float2(c, s);
}

static __device__ __forceinline__ int modL(int x) { x %= SL; return x < 0 ? x + SL : x; }

// packed complex in-place multiply: (ar,ai) *= (br,bi)
#define CMUL(ar, ai, br, bi) do {            \
    uint64_t _m, _nr;                        \
    F2MUL(_m, ai, bi); _m ^= SGNMASK;        \
    F2FMA(_nr, ar, br, _m);                  \
    F2MUL(_m, ai, br);                       \
    F2FMA(ai, ar, bi, _m);                   \
    ar = _nr;                                \
} while (0)

// Evaluate one residue class: acc_j += (+-) W * seed * phi^j, j = 0..S-1
// (Chebyshev 3-term chain with alternating-sign substitution; signs are
//  consistent per j across iterations, and only |acc|^2 is consumed.)
template <int S>
static __device__ __forceinline__ void eval_class(
    uint64_t Wr, uint64_t Wi, uint64_t sr, uint64_t si,
    uint64_t phir, uint64_t phii, uint64_t tc, uint64_t ntc,
    uint64_t* accr, uint64_t* acci)
{
    uint64_t m, v0r, v0i;
    F2MUL(m, Wi, si); m ^= SGNMASK;
    F2FMA(v0r, Wr, sr, m);
    F2MUL(m, Wi, sr);
    F2FMA(v0i, Wr, si, m);
    F2ADD(accr[0], accr[0], v0r);
    F2ADD(acci[0], acci[0], v0i);

    uint64_t v1r, v1i;
    F2MUL(m, v0i, phii); m ^= SGNMASK;
    F2FMA(v1r, v0r, phir, m);
    F2MUL(m, v0i, phir);
    F2FMA(v1i, v0r, phii, m);
    F2ADD(accr[1], accr[1], v1r);
    F2ADD(acci[1], acci[1], v1i);

    uint64_t pr = v0r, pi_ = v0i, cr = v1r, ci_ = v1i;
#pragma unroll
    for (int j = 2; j < S; j++) {
        uint64_t co = (j & 1) ? tc : ntc;   // -tc, +tc, -tc, ...
        uint64_t nr, ni;
        F2FMA(nr, co, cr, pr);
        F2FMA(ni, co, ci_, pi_);
        pr = cr; pi_ = ci_; cr = nr; ci_ = ni;
        F2ADD(accr[j], accr[j], nr);
        F2ADD(acci[j], acci[j], ni);
    }
}

// warp-reduce packed complex sum, lane0 writes |X|^2 to global
static __device__ __forceinline__ void reduce_pow(
    float* dst, uint64_t ar, uint64_t ai, int lane)
{
    float rr = lo2(ar) + hi2(ar);
    float ii = lo2(ai) + hi2(ai);
#pragma unroll
    for (int o = 16; o > 0; o >>= 1) {
        rr += __shfl_xor_sync(0xFFFFFFFFu, rr, o);
        ii += __shfl_xor_sync(0xFFFFFFFFu, ii, o);
    }
    if (lane == 0) *dst = rr * rr + ii * ii;
}

// ---------------------------------------------------------------------------
// kA: radix-4-decimated candidate DFT, one residue-class pass per block.
//   blockIdx.x = sb*2 + pass; 128 threads, warp = antenna.
//   X(n0+d) = sum_p e^{i th (n0+d) p} * W_p[d mod 4],
//   W_p[k]  = sum_q x_{p+816q} i^{kq}  (multiplier-free FFT4; th*816 = pi/2,
//   n0 = 272*j is divisible by 4 so the chirp q-factor vanishes)
// ---------------------------------------------------------------------------
__global__ void __launch_bounds__(128)
kA(const float* __restrict__ lsr, const float* __restrict__ lsi,
   const int* __restrict__ cs) {
    const int blk  = blockIdx.x;
    const int sb   = blk >> 1;
    const int pass = blk & 1;
    const int s    = sb / BB;
    const int a    = threadIdx.x >> 5;   // warp = antenna
    const int lane = threadIdx.x & 31;

    const int ideal = ((KK - cs[s]) % KK) * LPK;   // in [0, SL), multiple of 4
    const int n0    = ideal;

    const float* br = lsr + ((size_t)sb * AA + a) * SL;
    const float* bi = lsi + ((size_t)sb * AA + a) * SL;

    const int p0 = 2 * lane;     // packed pair (p0, p0+1); advance 64/iter

    const float2 psc = phasor(256 % SL);
    const uint64_t pstr = splat(psc.x), psti = splat(psc.y);

    float* powbase = g_pows + ((size_t)sb * AA + a) * NOFF;

    if (pass == 0) {
        // classes k=0 (d = -8..8 step4, S=5), k=2 (d = -10..10 step4, S=6)
        uint64_t a0r[5], a0i[5], a2r[6], a2i[6];
#pragma unroll
        for (int j = 0; j < 5; j++) { a0r[j] = a0i[j] = 0ULL; }
#pragma unroll
        for (int j = 0; j < 6; j++) { a2r[j] = a2i[j] = 0ULL; }

        const int f0 = n0 - 8, f2 = n0 - 10;
        float2 ea = phasor(modL(f0 * p0)), eb = phasor(modL(f0 * (p0 + 1)));
        uint64_t s0r = pk2(ea.x, eb.x), s0i = pk2(ea.y, eb.y);
        ea = phasor(modL(f2 * p0)); eb = phasor(modL(f2 * (p0 + 1)));
        uint64_t s2r = pk2(ea.x, eb.x), s2i = pk2(ea.y, eb.y);

        float2 st = phasor(modL(f0 * 64));
        uint64_t st0r = splat(st.x), st0i = splat(st.y);
        st = phasor(modL(f2 * 64));
        uint64_t st2r = splat(st.x), st2i = splat(st.y);

        float2 pa = phasor(modL(4 * p0)), pb = phasor(modL(4 * p0 + 4));
        uint64_t phir = pk2(pa.x, pb.x), phii = pk2(pa.y, pb.y);

        int p = p0;
#pragma unroll 1
        for (int it = 0; it < 13; ++it, p += 64) {
            const bool v = (p < PDIM);
            uint64_t xr0 = v ? *(const uint64_t*)(br + p)            : 0ULL;
            uint64_t xr1 = v ? *(const uint64_t*)(br + p + PDIM)     : 0ULL;
            uint64_t xr2 = v ? *(const uint64_t*)(br + p + 2 * PDIM) : 0ULL;
            uint64_t xr3 = v ? *(const uint64_t*)(br + p + 3 * PDIM) : 0ULL;
            uint64_t xi0 = v ? *(const uint64_t*)(bi + p)            : 0ULL;
            uint64_t xi1 = v ? *(const uint64_t*)(bi + p + PDIM)     : 0ULL;
            uint64_t xi2 = v ? *(const uint64_t*)(bi + p + 2 * PDIM) : 0ULL;
            uint64_t xi3 = v ? *(const uint64_t*)(bi + p + 3 * PDIM) : 0ULL;

            // half-FFT4 (even): W0 = (z0+z2)+(z1+z3), W2 = (z0+z2)-(z1+z3)
            uint64_t t0r, t0i, t2r, t2i, W0r, W0i, W2r, W2i;
            F2ADD(t0r, xr0, xr2); F2ADD(t0i, xi0, xi2);
            F2ADD(t2r, xr1, xr3); F2ADD(t2i, xi1, xi3);
            F2ADD(W0r, t0r, t2r); F2ADD(W0i, t0i, t2i);
            uint64_t n1 = t2r ^ SGNMASK, n2 = t2i ^ SGNMASK;
            F2ADD(W2r, t0r, n1); F2ADD(W2i, t0i, n2);

            uint64_t tc, ntc;
            F2ADD(tc, phir, phir); ntc = tc ^ SGNMASK;

            eval_class<5>(W0r, W0i, s0r, s0i, phir, phii, tc, ntc, a0r, a0i);
            eval_class<6>(W2r, W2i, s2r, s2i, phir, phii, tc, ntc, a2r, a2i);

            CMUL(s0r, s0i, st0r, st0i);
            CMUL(s2r, s2i, st2r, st2i);
            CMUL(phir, phii, pstr, psti);
        }
#pragma unroll
        for (int j = 0; j < 5; j++) reduce_pow(powbase + 2 + 4 * j, a0r[j], a0i[j], lane);
#pragma unroll
        for (int j = 0; j < 6; j++) reduce_pow(powbase + 0 + 4 * j, a2r[j], a2i[j], lane);
    } else {
        // classes k=1 (d = -7..9 step4, S=5), k=3 (d = -9..7 step4, S=5)
        uint64_t a1r[5], a1i[5], a3r[5], a3i[5];
#pragma unroll
        for (int j = 0; j < 5; j++) { a1r[j] = a1i[j] = 0ULL; a3r[j] = a3i[j] = 0ULL; }

        const int f1 = n0 - 7, f3 = n0 - 9;
        float2 ea = phasor(modL(f1 * p0)), eb = phasor(modL(f1 * (p0 + 1)));
        uint64_t s1r = pk2(ea.x, eb.x), s1i = pk2(ea.y, eb.y);
        ea = phasor(modL(f3 * p0)); eb = phasor(modL(f3 * (p0 + 1)));
        uint64_t s3r = pk2(ea.x, eb.x), s3i = pk2(ea.y, eb.y);

        float2 st = phasor(modL(f1 * 64));
        uint64_t st1r = splat(st.x), st1i = splat(st.y);
        st = phasor(modL(f3 * 64));
        uint64_t st3r = splat(st.x), st3i = splat(st.y);

        float2 pa = phasor(modL(4 * p0)), pb = phasor(modL(4 * p0 + 4));
        uint64_t phir = pk2(pa.x, pb.x), phii = pk2(pa.y, pb.y);

        int p = p0;
#pragma unroll 1
        for (int it = 0; it < 13; ++it, p += 64) {
            const bool v = (p < PDIM);
            uint64_t xr0 = v ? *(const uint64_t*)(br + p)            : 0ULL;
            uint64_t xr1 = v ? *(const uint64_t*)(br + p + PDIM)     : 0ULL;
            uint64_t xr2 = v ? *(const uint64_t*)(br + p + 2 * PDIM) : 0ULL;
            uint64_t xr3 = v ? *(const uint64_t*)(br + p + 3 * PDIM) : 0ULL;
            uint64_t xi0 = v ? *(const uint64_t*)(bi + p)            : 0ULL;
            uint64_t xi1 = v ? *(const uint64_t*)(bi + p + PDIM)     : 0ULL;
            uint64_t xi2 = v ? *(const uint64_t*)(bi + p + 2 * PDIM) : 0ULL;
            uint64_t xi3 = v ? *(const uint64_t*)(bi + p + 3 * PDIM) : 0ULL;

            // half-FFT4 (odd): t1 = z0-z2, t3 = z1-z3, W1 = t1+i t3, W3 = t1-i t3
            uint64_t nxr2 = xr2 ^ SGNMASK, nxi2 = xi2 ^ SGNMASK;
            uint64_t nxr3 = xr3 ^ SGNMASK, nxi3 = xi3 ^ SGNMASK;
            uint64_t t1r, t1i, t3r, t3i;
            F2ADD(t1r, xr0, nxr2); F2ADD(t1i, xi0, nxi2);
            F2ADD(t3r, xr1, nxr3); F2ADD(t3i, xi1, nxi3);
            uint64_t nt3i = t3i ^ SGNMASK, nt3r = t3r ^ SGNMASK;
            uint64_t W1r, W1i, W3r, W3i;
            F2ADD(W1r, t1r, nt3i); F2ADD(W1i, t1i, t3r);
            F2ADD(W3r, t1r, t3i);  F2ADD(W3i, t1i, nt3r);

            uint64_t tc, ntc;
            F2ADD(tc, phir, phir); ntc = tc ^ SGNMASK;

            eval_class<5>(W1r, W1i, s1r, s1i, phir, phii, tc, ntc, a1r, a1i);
            eval_class<5>(W3r, W3i, s3r, s3i, phir, phii, tc, ntc, a3r, a3i);

            CMUL(s1r, s1i, st1r, st1i);
            CMUL(s3r, s3i, st3r, st3i);
            CMUL(phir, phii, pstr, psti);
        }
#pragma unroll
        for (int j = 0; j < 5; j++) reduce_pow(powbase + 3 + 4 * j, a1r[j], a1i[j], lane);
#pragma unroll
        for (int j = 0; j < 5; j++) reduce_pow(powbase + 1 + 4 * j, a3r[j], a3i[j], lane);
    }
}

// ---------------------------------------------------------------------------
// kB: argmax over candidate powers, then phase B OCC averaging (L2-hot data).
//   One block per (s,b), 128 threads.
// ---------------------------------------------------------------------------
__global__ void __launch_bounds__(128)
kB(const float* __restrict__ lsr, const float* __restrict__ lsi,
   const int* __restrict__ cs) {
    const int sb = blockIdx.x;
    const int s  = sb / BB;

    __shared__ float shpow[NOFF];
    __shared__ int   sh_mm;

    if (threadIdx.x < NOFF) {
        const float* pb = g_pows + (size_t)sb * AA * NOFF + threadIdx.x;
        shpow[threadIdx.x] = pb[0] + pb[NOFF] + pb[2 * NOFF] + pb[3 * NOFF];
    }
    __syncthreads();

    if (threadIdx.x == 0) {
        const int ideal = ((KK - cs[s]) % KK) * LPK;
        int   best = 0;
        float bp   = shpow[0];
        for (int j = 1; j < NOFF; j++)
            if (shpow[j] > bp) { bp = shpow[j]; best = j; }  // first-max tie rule
        int toff = best - 10;
        int mmv  = modL(toff + ideal);
        g_m[sb]  = mmv;
        g_tt[sb] = modL(toff);
        sh_mm    = mmv;
    }
    __syncthreads();

    // phase B: h_avg[s,b,a,r] = (1/4) sum_j ls[.,4r+j] * e^{i th mm (4r+j)}
    const int mmv = sh_mm;
    float2 msv = phasor(mmv);                       // e^{i th mm}
    float2 spv = phasor((mmv * 512) % SL);          // r += 128 step (mm*4*128)
    float2 sd0 = phasor((mmv * 4 * (int)threadIdx.x) % SL);

#pragma unroll
    for (int a2 = 0; a2 < AA; a2++) {
        const float* br2 = lsr + ((size_t)sb * AA + a2) * SL;
        const float* bi2 = lsi + ((size_t)sb * AA + a2) * SL;
        float2* ho = g_havg + ((size_t)sb * AA + a2) * RR;
        float pc = sd0.x, ps = sd0.y;
        for (int r = threadIdx.x; r < RR; r += 128) {
            int l0 = 4 * r;
            float4 xr = *(const float4*)(br2 + l0);
            float4 xi = *(const float4*)(bi2 + l0);
            float xrv[4] = {xr.x, xr.y, xr.z, xr.w};
            float xiv[4] = {xi.x, xi.y, xi.z, xi.w};
            float qc = pc, qs = ps;
            float sr = 0.0f, si = 0.0f;
#pragma unroll
            for (int j = 0; j < 4; j++) {
                sr += xrv[j] * qc - xiv[j] * qs;
                si += xrv[j] * qs + xiv[j] * qc;
                if (j < 3) {
                    float nc = qc * msv.x - qs * msv.y;
                    float ns = qc * msv.y + qs * msv.x;
                    qc = nc; qs = ns;
                }
            }
            ho[r] = make_float2(sr * 0.25f, si * 0.25f);
            float nc = pc * spv.x - ps * spv.y;
            float ns = pc * spv.y + ps * spv.x;
            pc = nc; ps = ns;
        }
    }
}

// ---------------------------------------------------------------------------
// k_final: warp-per-stream over a 128-l tile for one (b,a).
// ---------------------------------------------------------------------------
__global__ void __launch_bounds__(256)
k_final(const float* __restrict__ lsr, const float* __restrict__ lsi,
        float* __restrict__ out) {
    const int blk  = blockIdx.x;
    const int ba   = blk / NTILE;
    const int tile = blk % NTILE;
    const int a    = ba % AA;
    const int b    = ba / AA;
    const int s    = threadIdx.x >> 5;   // warp = stream
    const int lane = threadIdx.x & 31;

    const int lbase = tile * TILE;
    const int l0    = lbase + lane * 4;
    const bool act  = (l0 < SL);

    __shared__ float shc[SS][2 * TILE];   // recon contributions
    __shared__ float shres[2 * TILE];     // residual

    const int sb = s * BB + b;
    const int mm = g_m[sb];
    const int tt = g_tt[sb];
    const float2* hv = g_havg + ((size_t)sb * AA + a) * RR;

    float hr[4], hi[4], pr[4], pi[4];

    if (act) {
        int g = l0 >> 2;
        float2 hm = hv[max(g - 1, 0)];
        float2 h0 = hv[g];
        float2 hp = hv[min(g + 1, RR - 1)];

        float f0 = (g > 0)      ? 0.625f : 0.0f;
        float f1 = (g > 0)      ? 0.875f : 0.0f;
        float f2 = (g < RR - 1) ? 0.125f : 0.0f;
        float f3 = (g < RR - 1) ? 0.375f : 0.0f;

        hr[0] = hm.x * (1.0f - f0) + h0.x * f0;  hi[0] = hm.y * (1.0f - f0) + h0.y * f0;
        hr[1] = hm.x * (1.0f - f1) + h0.x * f1;  hi[1] = hm.y * (1.0f - f1) + h0.y * f1;
        hr[2] = h0.x * (1.0f - f2) + hp.x * f2;  hi[2] = h0.y * (1.0f - f2) + hp.y * f2;
        hr[3] = h0.x * (1.0f - f3) + hp.x * f3;  hi[3] = h0.y * (1.0f - f3) + hp.y * f3;

        // mm*l0 <= 3263*3263 ~ 10.6M: int32-safe
        float2 pm = phasor((mm * l0) % SL);
        float2 ms = phasor(mm);
        float pmc = pm.x, pms = pm.y;

        float cr[4], cc[4];
#pragma unroll
        for (int j = 0; j < 4; j++) {
            pr[j] = pmc; pi[j] = pms;
            cr[j] = hr[j] * pmc + hi[j] * pms;
            cc[j] = hi[j] * pmc - hr[j] * pms;
            if (j < 3) {
                float nc = pmc * ms.x - pms * ms.y;
                float ns = pmc * ms.y + pms * ms.x;
                pmc = nc; pms = ns;
            }
        }
        float4* dst = (float4*)&shc[s][lane * 8];
        dst[0] = make_float4(cr[0], cc[0], cr[1], cc[1]);
        dst[1] = make_float4(cr[2], cc[2], cr[3], cc[3]);
    }
    __syncthreads();

    // residual reduction
    {
        int ll   = threadIdx.x >> 1;
        int comp = threadIdx.x & 1;
        int lg   = lbase + ll;
        if (lg < SL) {
            float sum = 0.0f;
#pragma unroll
            for (int ss2 = 0; ss2 < SS; ss2++) sum += shc[ss2][ll * 2 + comp];
            const float* ls0 = comp ? lsi : lsr;
            shres[ll * 2 + comp] = ls0[(size_t)ba * SL + lg] - sum;
        }
    }
    __syncthreads();

    if (act) {
        float2 pt = phasor((tt * l0) % SL);
        float2 ts = phasor(tt);
        float ptc = pt.x, pts = pt.y;

        float4 r01 = *(float4*)&shres[lane * 8];
        float4 r23 = *(float4*)&shres[lane * 8 + 4];
        float rres[4] = {r01.x, r01.z, r23.x, r23.z};
        float rims[4] = {r01.y, r01.w, r23.y, r23.w};

        float4 outr, outi;
        float* orp = &outr.x;
        float* oip = &outi.x;
#pragma unroll
        for (int j = 0; j < 4; j++) {
            float wr = hr[j] + rres[j] * pr[j] - rims[j] * pi[j];
            float wi = hi[j] + rres[j] * pi[j] + rims[j] * pr[j];
            orp[j] = wr * ptc + wi * pts;
            oip[j] = wi * ptc - wr * pts;
            if (j < 3) {
                float nc = ptc * ts.x - pts * ts.y;
                float ns = ptc * ts.y + pts * ts.x;
                ptc = nc; pts = ns;
            }
        }

        const size_t TOT = (size_t)SS * BB * AA * SL;
        size_t off = ((size_t)sb * AA + a) * SL + (size_t)l0;
        *(float4*)(out + off)       = outr;
        *(float4*)(out + TOT + off) = outi;
    }
}

// ---------------------------------------------------------------------------
extern "C" void kernel_launch(void* const* d_in, const int* in_sizes, int n_in,
                              void* d_out, int out_size) {
    (void)in_sizes; (void)n_in; (void)out_size;
    const float* lsr = (const float*)d_in[0];
    const float* lsi = (const float*)d_in[1];
    const int*   cs  = (const int*)d_in[2];
    float*       out = (float*)d_out;

    kA<<<SS * BB * 2, 128>>>(lsr, lsi, cs);
    kB<<<SS * BB, 128>>>(lsr, lsi, cs);
    k_final<<<BB * AA * NTILE, 256>>>(lsr, lsi, out);
}